// round 16
// baseline (speedup 1.0000x reference)
#include <cuda_runtime.h>
#include <cuda_fp16.h>
#include <cstdint>

// ---------------------------------------------------------------------------
// update_e: SchNet CFConv edge message — fp16 mma.sync, register-resident h.
//   C    = 0.5*(cos(pi*d/10)+1)
//   h    = softplus(dist_emb @ mlp1_w^T + b1) - log(2)
//   W    = (h @ mlp2_w^T + b2) * C
//   out  = (v @ lin_w^T)[j] * W
//
// R16: 32-edge warp tile (two 16-row m-blocks share GEMM2 B fragments ->
// weight ldmatrix traffic per edge cut 1.5x; L1-bound per R15 ncu).
//   - warp-autonomous, barrier-free main loop (16 warps/SM drift freely)
//   - h register-resident (GEMM1 acc == GEMM2 A fragment layout)
//   - emb single-buffered per warp; next-group cp.async issued right after
//     GEMM1 consumes the buffer (overlaps GEMM2+epilogue)
//   - GEMM2 in 8 n16-tiles with fused epilogue (register pressure < 128)
// Math identical to R11..R15 (fp16 operands, fp32 accum, rel_err 4.2e-4).
// ---------------------------------------------------------------------------

#define SHIFT_LN2       0.69314718055994530942f
#define PI_OVER_CUTOFF  0.31415926535897932385f

__device__ float g_vl[50000 * 128];

extern __shared__ uint32_t smw[];

// ---- SMEM word-offsets (edge kernel) ----
static constexpr int ST1 = 36;     // W1 row stride (words): 32 data + 4 pad
static constexpr int ST2 = 68;     // W2 row stride (words): 64 data + 4 pad
static constexpr int STE = 54;     // emb fp32 row stride (floats): 50 + 4 pad
static constexpr int W1S = 0;                        // [128][36] fp16x2
static constexpr int W2S = W1S + 128 * ST1;          // [128][68] fp16x2
static constexpr int B1W = W2S + 128 * ST2;          // 128 f32
static constexpr int B2W = B1W + 128;                // 128 f32
static constexpr int EMBS = B2W + 128;               // 8 warps x [32][54] f32
static constexpr int EMBBUF = 32 * STE;              // 1728 words per warp
static constexpr int SMEM_WORDS = EMBS + 8 * EMBBUF; // 27392 w = 109568 B

// ---------------------------- helpers --------------------------------------
__device__ __forceinline__ float softplus_fast(float x) {
    return __logf(1.f + __expf(x));
}
__device__ __forceinline__ uint32_t cvt2(float x0, float x1) {
    __half2 p = __halves2half2(__float2half(x0), __float2half(x1));
    return *reinterpret_cast<uint32_t*>(&p);
}
__device__ __forceinline__ uint32_t smem_addr(const void* p) {
    uint32_t a;
    asm("{ .reg .u64 t; cvta.to.shared.u64 t, %1; cvt.u32.u64 %0, t; }"
        : "=r"(a) : "l"(p));
    return a;
}
__device__ __forceinline__ void ldm_x4(uint32_t& r0, uint32_t& r1,
                                       uint32_t& r2, uint32_t& r3, uint32_t addr) {
    asm volatile("ldmatrix.sync.aligned.m8n8.x4.shared.b16 {%0,%1,%2,%3}, [%4];"
                 : "=r"(r0), "=r"(r1), "=r"(r2), "=r"(r3) : "r"(addr));
}
__device__ __forceinline__ void mma16816(float d[4], const uint32_t a[4], const uint32_t b[2]) {
    asm volatile(
        "mma.sync.aligned.m16n8k16.row.col.f32.f16.f16.f32 "
        "{%0,%1,%2,%3}, {%4,%5,%6,%7}, {%8,%9}, {%0,%1,%2,%3};"
        : "+f"(d[0]), "+f"(d[1]), "+f"(d[2]), "+f"(d[3])
        : "r"(a[0]), "r"(a[1]), "r"(a[2]), "r"(a[3]), "r"(b[0]), "r"(b[1]));
}
__device__ __forceinline__ void cp8(uint32_t dst, const void* src) {
    asm volatile("cp.async.ca.shared.global [%0], [%1], 8;" :: "r"(dst), "l"(src));
}
#define CP_COMMIT() asm volatile("cp.async.commit_group;" ::: "memory")
#define CP_WAIT(n)  asm volatile("cp.async.wait_group %0;" :: "n"(n) : "memory")

// ------------------------- Kernel A: vl = v @ lin_w^T -----------------------
__global__ void __launch_bounds__(256, 1)
vl_kernel(const float* __restrict__ v, const float* __restrict__ lin_w, int nrows)
{
    float* smem = (float*)smw;
    float* wT = smem;               // [128][128]
    float* a  = smem + 128 * 128;   // [128][132]
    const int tid = threadIdx.x;
    const int r0  = blockIdx.x * 128;

    for (int i = tid; i < 128 * 128; i += 256) {
        int f = i >> 7, k = i & 127;
        wT[k * 128 + f] = lin_w[i];
    }
    for (int i = tid; i < 128 * 128; i += 256) {
        int r = i >> 7, k = i & 127;
        int rg = r0 + r;
        a[r * 132 + k] = (rg < nrows) ? v[(size_t)rg * 128 + k] : 0.f;
    }
    __syncthreads();

    const int tx = tid & 15, ty = tid >> 4;
    const int f0 = tx * 8, rr0 = ty * 8;

    float acc[8][8];
    #pragma unroll
    for (int i = 0; i < 8; i++)
        #pragma unroll
        for (int j = 0; j < 8; j++) acc[i][j] = 0.f;

    #pragma unroll 8
    for (int k = 0; k < 128; k++) {
        float4 b0 = *reinterpret_cast<const float4*>(&wT[k * 128 + f0]);
        float4 b1 = *reinterpret_cast<const float4*>(&wT[k * 128 + f0 + 4]);
        #pragma unroll
        for (int i = 0; i < 8; i++) {
            float av = a[(rr0 + i) * 132 + k];
            acc[i][0] += av * b0.x; acc[i][1] += av * b0.y;
            acc[i][2] += av * b0.z; acc[i][3] += av * b0.w;
            acc[i][4] += av * b1.x; acc[i][5] += av * b1.y;
            acc[i][6] += av * b1.z; acc[i][7] += av * b1.w;
        }
    }

    #pragma unroll
    for (int i = 0; i < 8; i++) {
        int rg = r0 + rr0 + i;
        if (rg < nrows) {
            *reinterpret_cast<float4*>(&g_vl[(size_t)rg * 128 + f0]) =
                make_float4(acc[i][0], acc[i][1], acc[i][2], acc[i][3]);
            *reinterpret_cast<float4*>(&g_vl[(size_t)rg * 128 + f0 + 4]) =
                make_float4(acc[i][4], acc[i][5], acc[i][6], acc[i][7]);
        }
    }
}

// -------------- Kernel B: warp-autonomous persistent edge kernel ------------
__global__ void __launch_bounds__(256, 2)
edge_mma_kernel(const float* __restrict__ dist,
                const float* __restrict__ dist_emb,
                const int* __restrict__ edge_index,   // int32, row 0 = source
                const float* __restrict__ mlp1_w, const float* __restrict__ mlp1_b,
                const float* __restrict__ mlp2_w, const float* __restrict__ mlp2_b,
                float* __restrict__ out, int E, int ngroups)
{
    const int tid  = threadIdx.x;
    const int lane = tid & 31;
    const int wid  = tid >> 5;       // 0..7
    const int g    = lane >> 2;      // 0..7
    const int t    = lane & 3;       // 0..3

    const uint32_t sbase = smem_addr(smw);

    // ldmatrix lane addressing (x4: 16 rows x 16 fp16 cols)
    const int sub = lane >> 3, lr = lane & 7;
    const int rowoff = ((sub & 1) << 3) + lr;     // 0..15
    const int kcol   = (sub >> 1) << 2;           // 0 or 4 words

    float* b1f = (float*)(smw + B1W);
    float* b2f = (float*)(smw + B2W);

    // ---- zero W1 K-pad (fp16 k 50..63 must read as 0) ----
    for (int i = tid; i < 128 * ST1; i += 256) smw[W1S + i] = 0;
    __syncthreads();

    // ---- stage weights as fp16 (once per CTA) ----
    for (int i = tid; i < 128 * 25; i += 256) {          // w1: 128 x 50
        int f = i / 25, c = i - f * 25;
        float2 w = *(const float2*)(mlp1_w + (size_t)f * 50 + 2 * c);
        smw[W1S + f * ST1 + c] = cvt2(w.x, w.y);
    }
    for (int i = tid; i < 128 * 64; i += 256) {          // w2: 128 x 128
        int f = i >> 6, c = i & 63;
        float2 w = *(const float2*)(mlp2_w + (size_t)f * 128 + 2 * c);
        smw[W2S + f * ST2 + c] = cvt2(w.x, w.y);
    }
    if (tid < 128) { b1f[tid] = mlp1_b[tid]; b2f[tid] = mlp2_b[tid]; }
    __syncthreads();
    // ======= main loop is barrier-free: all mutable SMEM is warp-private ====

    const int embW = EMBS + wid * EMBBUF;         // this warp's emb buffer
    const int gwid    = blockIdx.x * 8 + wid;
    const int gstride = gridDim.x * 8;

    // ---- prologue: prefetch first group (row = lane, 50 floats) ----
    if (gwid < ngroups) {
        int e = gwid * 32 + lane;
        if (e < E) {
            const float* src = dist_emb + (size_t)e * 50;
            uint32_t dst = sbase + 4u * (uint32_t)(embW + lane * STE);
            #pragma unroll
            for (int c = 0; c < 25; c++) cp8(dst + c * 8, src + c * 2);
        }
    }
    CP_COMMIT();

    const uint32_t w1B = sbase + 4u * (uint32_t)(W1S + rowoff * ST1 + kcol);
    const uint32_t w2B = sbase + 4u * (uint32_t)(W2S + rowoff * ST2 + kcol);

    for (int grp = gwid; grp < ngroups; grp += gstride) {
        CP_WAIT(0);            // emb for this group landed
        __syncwarp();

        const int ebase = grp * 32;

        // ---- per-edge scalars: rows g, g+8, g+16, g+24 (redundant over t) --
        float Cv[4]; int jv[4];
        #pragma unroll
        for (int q = 0; q < 4; q++) {
            int e = ebase + q * 8 + g;
            if (e < E) {
                Cv[q] = 0.5f * (__cosf(dist[e] * PI_OVER_CUTOFF) + 1.f);
                jv[q] = edge_index[e];
            } else { Cv[q] = 0.f; jv[q] = 0; }
        }

        // ========== GEMM1 per m-block -> register-resident A2 fragments =====
        uint32_t a2[2][8][4];
        const float* eb = (const float*)(smw + embW);
        #pragma unroll
        for (int mb = 0; mb < 2; mb++) {
            float acc1[16][4];
            #pragma unroll
            for (int nt = 0; nt < 16; nt++)
                #pragma unroll
                for (int q = 0; q < 4; q++) acc1[nt][q] = 0.f;

            const int rb = mb * 16 + g;
            #pragma unroll
            for (int s = 0; s < 4; s++) {
                uint32_t a[4];
                if (s < 3) {
                    int k0 = s * 16 + 2 * t;
                    float2 p0 = *(const float2*)(eb + rb * STE + k0);
                    float2 p1 = *(const float2*)(eb + (rb + 8) * STE + k0);
                    float2 p2 = *(const float2*)(eb + rb * STE + k0 + 8);
                    float2 p3 = *(const float2*)(eb + (rb + 8) * STE + k0 + 8);
                    a[0] = cvt2(p0.x, p0.y); a[1] = cvt2(p1.x, p1.y);
                    a[2] = cvt2(p2.x, p2.y); a[3] = cvt2(p3.x, p3.y);
                } else {
                    if (t == 0) {
                        float2 p0 = *(const float2*)(eb + rb * STE + 48);
                        float2 p1 = *(const float2*)(eb + (rb + 8) * STE + 48);
                        a[0] = cvt2(p0.x, p0.y); a[1] = cvt2(p1.x, p1.y);
                    } else { a[0] = 0; a[1] = 0; }
                    a[2] = 0; a[3] = 0;
                }
                const uint32_t kb = (uint32_t)(s * 8) * 4u;
                #pragma unroll
                for (int np = 0; np < 8; np++) {
                    uint32_t b0, b1, b2, b3;
                    ldm_x4(b0, b1, b2, b3, w1B + kb + (uint32_t)(np * 16 * ST1) * 4u);
                    uint32_t be[2] = { b0, b2 };
                    uint32_t bo[2] = { b1, b3 };
                    mma16816(acc1[2 * np],     a, be);
                    mma16816(acc1[2 * np + 1], a, bo);
                }
            }

            // h = softplus(acc1 + b1) - ln2 -> fp16 A fragments (registers)
            #pragma unroll
            for (int s = 0; s < 8; s++) {
                int f0 = 16 * s + 2 * t;
                float2 ba = *(const float2*)(b1f + f0);
                float2 bc = *(const float2*)(b1f + f0 + 8);
                a2[mb][s][0] = cvt2(softplus_fast(acc1[2 * s][0] + ba.x) - SHIFT_LN2,
                                    softplus_fast(acc1[2 * s][1] + ba.y) - SHIFT_LN2);
                a2[mb][s][1] = cvt2(softplus_fast(acc1[2 * s][2] + ba.x) - SHIFT_LN2,
                                    softplus_fast(acc1[2 * s][3] + ba.y) - SHIFT_LN2);
                a2[mb][s][2] = cvt2(softplus_fast(acc1[2 * s + 1][0] + bc.x) - SHIFT_LN2,
                                    softplus_fast(acc1[2 * s + 1][1] + bc.y) - SHIFT_LN2);
                a2[mb][s][3] = cvt2(softplus_fast(acc1[2 * s + 1][2] + bc.x) - SHIFT_LN2,
                                    softplus_fast(acc1[2 * s + 1][3] + bc.y) - SHIFT_LN2);
            }
        }

        // ---- emb consumed: prefetch next group into the same buffer -------
        {
            int gn = grp + gstride;
            if (gn < ngroups) {
                int e = gn * 32 + lane;
                if (e < E) {
                    const float* src = dist_emb + (size_t)e * 50;
                    uint32_t dst = sbase + 4u * (uint32_t)(embW + lane * STE);
                    #pragma unroll
                    for (int c = 0; c < 25; c++) cp8(dst + c * 8, src + c * 2);
                }
            }
        }
        CP_COMMIT();

        // ====== GEMM2 in 8 n16-tiles, B shared across both m-blocks ========
        #pragma unroll
        for (int n16 = 0; n16 < 8; n16++) {
            float acc2[2][2][4];            // [m][n8][q]
            #pragma unroll
            for (int m = 0; m < 2; m++)
                #pragma unroll
                for (int n = 0; n < 2; n++)
                    #pragma unroll
                    for (int q = 0; q < 4; q++) acc2[m][n][q] = 0.f;

            #pragma unroll
            for (int s = 0; s < 8; s++) {
                uint32_t b0, b1, b2, b3;
                ldm_x4(b0, b1, b2, b3,
                       w2B + (uint32_t)(s * 8) * 4u + (uint32_t)(n16 * 16 * ST2) * 4u);
                uint32_t be[2] = { b0, b2 };
                uint32_t bo[2] = { b1, b3 };
                mma16816(acc2[0][0], a2[0][s], be);
                mma16816(acc2[0][1], a2[0][s], bo);
                mma16816(acc2[1][0], a2[1][s], be);
                mma16816(acc2[1][1], a2[1][s], bo);
            }

            // ---- fused epilogue for these 16 feats ----
            #pragma unroll
            for (int m = 0; m < 2; m++) {
                #pragma unroll
                for (int n = 0; n < 2; n++) {
                    int f = n16 * 16 + n * 8 + 2 * t;
                    float2 bb = *(const float2*)(b2f + f);
                    int elo = ebase + m * 16 + g;
                    int ehi = elo + 8;
                    if (elo < E) {
                        float2 vv = *(const float2*)(g_vl + (size_t)jv[2 * m] * 128 + f);
                        float2 o;
                        o.x = (acc2[m][n][0] + bb.x) * Cv[2 * m] * vv.x;
                        o.y = (acc2[m][n][1] + bb.y) * Cv[2 * m] * vv.y;
                        *(float2*)(out + (size_t)elo * 128 + f) = o;
                    }
                    if (ehi < E) {
                        float2 vv = *(const float2*)(g_vl + (size_t)jv[2 * m + 1] * 128 + f);
                        float2 o;
                        o.x = (acc2[m][n][2] + bb.x) * Cv[2 * m + 1] * vv.x;
                        o.y = (acc2[m][n][3] + bb.y) * Cv[2 * m + 1] * vv.y;
                        *(float2*)(out + (size_t)ehi * 128 + f) = o;
                    }
                }
            }
        }
    }
}

// ---------------------------------------------------------------------------
extern "C" void kernel_launch(void* const* d_in, const int* in_sizes, int n_in,
                              void* d_out, int out_size)
{
    const float* v          = (const float*)d_in[0];
    const float* dist       = (const float*)d_in[1];
    const float* dist_emb   = (const float*)d_in[2];
    const int*   edge_index = (const int*)d_in[3];   // int32 [2][E]
    const float* lin_w      = (const float*)d_in[4];
    const float* mlp1_w     = (const float*)d_in[5];
    const float* mlp1_b     = (const float*)d_in[6];
    const float* mlp2_w     = (const float*)d_in[7];
    const float* mlp2_b     = (const float*)d_in[8];
    float*       out        = (float*)d_out;

    const int N = in_sizes[0] / 128;
    const int E = in_sizes[1];
    const int ngroups = (E + 31) / 32;

    const size_t smemA = (size_t)(128 * 128 + 128 * 132) * sizeof(float);
    const size_t smemB = (size_t)SMEM_WORDS * 4;     // 109568 B

    cudaFuncSetAttribute(vl_kernel, cudaFuncAttributeMaxDynamicSharedMemorySize, (int)smemA);
    cudaFuncSetAttribute(edge_mma_kernel, cudaFuncAttributeMaxDynamicSharedMemorySize, (int)smemB);

    vl_kernel<<<(N + 127) / 128, 256, smemA>>>(v, lin_w, N);

    edge_mma_kernel<<<304, 256, smemB>>>(dist, dist_emb, edge_index,
                                         mlp1_w, mlp1_b, mlp2_w, mlp2_b,
                                         out, E, ngroups);
}

// round 17
// speedup vs baseline: 1.0387x; 1.0387x over previous
#include <cuda_runtime.h>
#include <cuda_fp16.h>
#include <cstdint>

// ---------------------------------------------------------------------------
// update_e: SchNet CFConv edge message — fp16 mma.sync, register-resident h.
//   C    = 0.5*(cos(pi*d/10)+1)
//   h    = softplus(dist_emb @ mlp1_w^T + b1) - log(2)
//   W    = (h @ mlp2_w^T + b2) * C
//   out  = (v @ lin_w^T)[j] * W
//
// R17: R16's 32-edge warp tile (GEMM2 B fragments shared across two
// m-blocks -> 1.5x less weight ldmatrix traffic) with the register spill
// fixed: GEMM1 runs in two 64-feat n-halves (acc1 = 32 regs instead of 64),
// converting to fp16 A2 fragments after each half. Peak live ~105 regs.
//   - warp-autonomous, barrier-free main loop
//   - h register-resident (GEMM1 acc == GEMM2 A fragment layout)
//   - emb single-buffered per warp; next-group cp.async overlaps GEMM2
// Math identical to R11..R16 (fp16 operands, fp32 accum, rel_err 4.2e-4).
// ---------------------------------------------------------------------------

#define SHIFT_LN2       0.69314718055994530942f
#define PI_OVER_CUTOFF  0.31415926535897932385f

__device__ float g_vl[50000 * 128];

extern __shared__ uint32_t smw[];

// ---- SMEM word-offsets (edge kernel) ----
static constexpr int ST1 = 36;     // W1 row stride (words): 32 data + 4 pad
static constexpr int ST2 = 68;     // W2 row stride (words): 64 data + 4 pad
static constexpr int STE = 54;     // emb fp32 row stride (floats): 50 + 4 pad
static constexpr int W1S = 0;                        // [128][36] fp16x2
static constexpr int W2S = W1S + 128 * ST1;          // [128][68] fp16x2
static constexpr int B1W = W2S + 128 * ST2;          // 128 f32
static constexpr int B2W = B1W + 128;                // 128 f32
static constexpr int EMBS = B2W + 128;               // 8 warps x [32][54] f32
static constexpr int EMBBUF = 32 * STE;              // 1728 words per warp
static constexpr int SMEM_WORDS = EMBS + 8 * EMBBUF; // 27392 w = 109568 B

// ---------------------------- helpers --------------------------------------
__device__ __forceinline__ float softplus_fast(float x) {
    return __logf(1.f + __expf(x));
}
__device__ __forceinline__ uint32_t cvt2(float x0, float x1) {
    __half2 p = __halves2half2(__float2half(x0), __float2half(x1));
    return *reinterpret_cast<uint32_t*>(&p);
}
__device__ __forceinline__ uint32_t smem_addr(const void* p) {
    uint32_t a;
    asm("{ .reg .u64 t; cvta.to.shared.u64 t, %1; cvt.u32.u64 %0, t; }"
        : "=r"(a) : "l"(p));
    return a;
}
__device__ __forceinline__ void ldm_x4(uint32_t& r0, uint32_t& r1,
                                       uint32_t& r2, uint32_t& r3, uint32_t addr) {
    asm volatile("ldmatrix.sync.aligned.m8n8.x4.shared.b16 {%0,%1,%2,%3}, [%4];"
                 : "=r"(r0), "=r"(r1), "=r"(r2), "=r"(r3) : "r"(addr));
}
__device__ __forceinline__ void mma16816(float d[4], const uint32_t a[4], const uint32_t b[2]) {
    asm volatile(
        "mma.sync.aligned.m16n8k16.row.col.f32.f16.f16.f32 "
        "{%0,%1,%2,%3}, {%4,%5,%6,%7}, {%8,%9}, {%0,%1,%2,%3};"
        : "+f"(d[0]), "+f"(d[1]), "+f"(d[2]), "+f"(d[3])
        : "r"(a[0]), "r"(a[1]), "r"(a[2]), "r"(a[3]), "r"(b[0]), "r"(b[1]));
}
__device__ __forceinline__ void cp8(uint32_t dst, const void* src) {
    asm volatile("cp.async.ca.shared.global [%0], [%1], 8;" :: "r"(dst), "l"(src));
}
#define CP_COMMIT() asm volatile("cp.async.commit_group;" ::: "memory")
#define CP_WAIT(n)  asm volatile("cp.async.wait_group %0;" :: "n"(n) : "memory")

// ------------------------- Kernel A: vl = v @ lin_w^T -----------------------
__global__ void __launch_bounds__(256, 1)
vl_kernel(const float* __restrict__ v, const float* __restrict__ lin_w, int nrows)
{
    float* smem = (float*)smw;
    float* wT = smem;               // [128][128]
    float* a  = smem + 128 * 128;   // [128][132]
    const int tid = threadIdx.x;
    const int r0  = blockIdx.x * 128;

    for (int i = tid; i < 128 * 128; i += 256) {
        int f = i >> 7, k = i & 127;
        wT[k * 128 + f] = lin_w[i];
    }
    for (int i = tid; i < 128 * 128; i += 256) {
        int r = i >> 7, k = i & 127;
        int rg = r0 + r;
        a[r * 132 + k] = (rg < nrows) ? v[(size_t)rg * 128 + k] : 0.f;
    }
    __syncthreads();

    const int tx = tid & 15, ty = tid >> 4;
    const int f0 = tx * 8, rr0 = ty * 8;

    float acc[8][8];
    #pragma unroll
    for (int i = 0; i < 8; i++)
        #pragma unroll
        for (int j = 0; j < 8; j++) acc[i][j] = 0.f;

    #pragma unroll 8
    for (int k = 0; k < 128; k++) {
        float4 b0 = *reinterpret_cast<const float4*>(&wT[k * 128 + f0]);
        float4 b1 = *reinterpret_cast<const float4*>(&wT[k * 128 + f0 + 4]);
        #pragma unroll
        for (int i = 0; i < 8; i++) {
            float av = a[(rr0 + i) * 132 + k];
            acc[i][0] += av * b0.x; acc[i][1] += av * b0.y;
            acc[i][2] += av * b0.z; acc[i][3] += av * b0.w;
            acc[i][4] += av * b1.x; acc[i][5] += av * b1.y;
            acc[i][6] += av * b1.z; acc[i][7] += av * b1.w;
        }
    }

    #pragma unroll
    for (int i = 0; i < 8; i++) {
        int rg = r0 + rr0 + i;
        if (rg < nrows) {
            *reinterpret_cast<float4*>(&g_vl[(size_t)rg * 128 + f0]) =
                make_float4(acc[i][0], acc[i][1], acc[i][2], acc[i][3]);
            *reinterpret_cast<float4*>(&g_vl[(size_t)rg * 128 + f0 + 4]) =
                make_float4(acc[i][4], acc[i][5], acc[i][6], acc[i][7]);
        }
    }
}

// -------------- Kernel B: warp-autonomous persistent edge kernel ------------
__global__ void __launch_bounds__(256, 2)
edge_mma_kernel(const float* __restrict__ dist,
                const float* __restrict__ dist_emb,
                const int* __restrict__ edge_index,   // int32, row 0 = source
                const float* __restrict__ mlp1_w, const float* __restrict__ mlp1_b,
                const float* __restrict__ mlp2_w, const float* __restrict__ mlp2_b,
                float* __restrict__ out, int E, int ngroups)
{
    const int tid  = threadIdx.x;
    const int lane = tid & 31;
    const int wid  = tid >> 5;       // 0..7
    const int g    = lane >> 2;      // 0..7
    const int t    = lane & 3;       // 0..3

    const uint32_t sbase = smem_addr(smw);

    // ldmatrix lane addressing (x4: 16 rows x 16 fp16 cols)
    const int sub = lane >> 3, lr = lane & 7;
    const int rowoff = ((sub & 1) << 3) + lr;     // 0..15
    const int kcol   = (sub >> 1) << 2;           // 0 or 4 words

    float* b1f = (float*)(smw + B1W);
    float* b2f = (float*)(smw + B2W);

    // ---- zero W1 K-pad (fp16 k 50..63 must read as 0) ----
    for (int i = tid; i < 128 * ST1; i += 256) smw[W1S + i] = 0;
    __syncthreads();

    // ---- stage weights as fp16 (once per CTA) ----
    for (int i = tid; i < 128 * 25; i += 256) {          // w1: 128 x 50
        int f = i / 25, c = i - f * 25;
        float2 w = *(const float2*)(mlp1_w + (size_t)f * 50 + 2 * c);
        smw[W1S + f * ST1 + c] = cvt2(w.x, w.y);
    }
    for (int i = tid; i < 128 * 64; i += 256) {          // w2: 128 x 128
        int f = i >> 6, c = i & 63;
        float2 w = *(const float2*)(mlp2_w + (size_t)f * 128 + 2 * c);
        smw[W2S + f * ST2 + c] = cvt2(w.x, w.y);
    }
    if (tid < 128) { b1f[tid] = mlp1_b[tid]; b2f[tid] = mlp2_b[tid]; }
    __syncthreads();
    // ======= main loop is barrier-free: all mutable SMEM is warp-private ====

    const int embW = EMBS + wid * EMBBUF;         // this warp's emb buffer
    const int gwid    = blockIdx.x * 8 + wid;
    const int gstride = gridDim.x * 8;

    // ---- prologue: prefetch first group (row = lane, 50 floats) ----
    if (gwid < ngroups) {
        int e = gwid * 32 + lane;
        if (e < E) {
            const float* src = dist_emb + (size_t)e * 50;
            uint32_t dst = sbase + 4u * (uint32_t)(embW + lane * STE);
            #pragma unroll
            for (int c = 0; c < 25; c++) cp8(dst + c * 8, src + c * 2);
        }
    }
    CP_COMMIT();

    const uint32_t w1B = sbase + 4u * (uint32_t)(W1S + rowoff * ST1 + kcol);
    const uint32_t w2B = sbase + 4u * (uint32_t)(W2S + rowoff * ST2 + kcol);

    for (int grp = gwid; grp < ngroups; grp += gstride) {
        CP_WAIT(0);            // emb for this group landed
        __syncwarp();

        const int ebase = grp * 32;

        // ---- per-edge scalars: rows g, g+8, g+16, g+24 (redundant over t) --
        float Cv[4]; int jv[4];
        #pragma unroll
        for (int q = 0; q < 4; q++) {
            int e = ebase + q * 8 + g;
            if (e < E) {
                Cv[q] = 0.5f * (__cosf(dist[e] * PI_OVER_CUTOFF) + 1.f);
                jv[q] = edge_index[e];
            } else { Cv[q] = 0.f; jv[q] = 0; }
        }

        // ====== GEMM1 per (m-block, n-half) -> register-resident A2 ========
        // acc1 is only 8x4 = 32 regs at a time (spill fix vs R16).
        uint32_t a2[2][8][4];
        const float* eb = (const float*)(smw + embW);
        #pragma unroll
        for (int mb = 0; mb < 2; mb++) {
            const int rb = mb * 16 + g;
            #pragma unroll
            for (int nh = 0; nh < 2; nh++) {
                float acc1[8][4];
                #pragma unroll
                for (int nt = 0; nt < 8; nt++)
                    #pragma unroll
                    for (int q = 0; q < 4; q++) acc1[nt][q] = 0.f;

                #pragma unroll
                for (int s = 0; s < 4; s++) {
                    uint32_t a[4];
                    if (s < 3) {
                        int k0 = s * 16 + 2 * t;
                        float2 p0 = *(const float2*)(eb + rb * STE + k0);
                        float2 p1 = *(const float2*)(eb + (rb + 8) * STE + k0);
                        float2 p2 = *(const float2*)(eb + rb * STE + k0 + 8);
                        float2 p3 = *(const float2*)(eb + (rb + 8) * STE + k0 + 8);
                        a[0] = cvt2(p0.x, p0.y); a[1] = cvt2(p1.x, p1.y);
                        a[2] = cvt2(p2.x, p2.y); a[3] = cvt2(p3.x, p3.y);
                    } else {
                        if (t == 0) {
                            float2 p0 = *(const float2*)(eb + rb * STE + 48);
                            float2 p1 = *(const float2*)(eb + (rb + 8) * STE + 48);
                            a[0] = cvt2(p0.x, p0.y); a[1] = cvt2(p1.x, p1.y);
                        } else { a[0] = 0; a[1] = 0; }
                        a[2] = 0; a[3] = 0;
                    }
                    const uint32_t kb = (uint32_t)(s * 8) * 4u;
                    #pragma unroll
                    for (int np = 0; np < 4; np++) {
                        int npg = nh * 4 + np;
                        uint32_t b0, b1, b2, b3;
                        ldm_x4(b0, b1, b2, b3, w1B + kb + (uint32_t)(npg * 16 * ST1) * 4u);
                        uint32_t be[2] = { b0, b2 };
                        uint32_t bo[2] = { b1, b3 };
                        mma16816(acc1[2 * np],     a, be);
                        mma16816(acc1[2 * np + 1], a, bo);
                    }
                }

                // h = softplus(acc1 + b1) - ln2 -> fp16 A fragments
                #pragma unroll
                for (int sl = 0; sl < 4; sl++) {
                    int s = nh * 4 + sl;
                    int f0 = 16 * s + 2 * t;
                    float2 ba = *(const float2*)(b1f + f0);
                    float2 bc = *(const float2*)(b1f + f0 + 8);
                    a2[mb][s][0] = cvt2(softplus_fast(acc1[2 * sl][0] + ba.x) - SHIFT_LN2,
                                        softplus_fast(acc1[2 * sl][1] + ba.y) - SHIFT_LN2);
                    a2[mb][s][1] = cvt2(softplus_fast(acc1[2 * sl][2] + ba.x) - SHIFT_LN2,
                                        softplus_fast(acc1[2 * sl][3] + ba.y) - SHIFT_LN2);
                    a2[mb][s][2] = cvt2(softplus_fast(acc1[2 * sl + 1][0] + bc.x) - SHIFT_LN2,
                                        softplus_fast(acc1[2 * sl + 1][1] + bc.y) - SHIFT_LN2);
                    a2[mb][s][3] = cvt2(softplus_fast(acc1[2 * sl + 1][2] + bc.x) - SHIFT_LN2,
                                        softplus_fast(acc1[2 * sl + 1][3] + bc.y) - SHIFT_LN2);
                }
            }
        }

        // ---- emb consumed: prefetch next group into the same buffer -------
        {
            int gn = grp + gstride;
            if (gn < ngroups) {
                int e = gn * 32 + lane;
                if (e < E) {
                    const float* src = dist_emb + (size_t)e * 50;
                    uint32_t dst = sbase + 4u * (uint32_t)(embW + lane * STE);
                    #pragma unroll
                    for (int c = 0; c < 25; c++) cp8(dst + c * 8, src + c * 2);
                }
            }
        }
        CP_COMMIT();

        // ====== GEMM2 in 8 n16-tiles, B shared across both m-blocks ========
        #pragma unroll
        for (int n16 = 0; n16 < 8; n16++) {
            float acc2[2][2][4];            // [m][n8][q]
            #pragma unroll
            for (int m = 0; m < 2; m++)
                #pragma unroll
                for (int n = 0; n < 2; n++)
                    #pragma unroll
                    for (int q = 0; q < 4; q++) acc2[m][n][q] = 0.f;

            #pragma unroll
            for (int s = 0; s < 8; s++) {
                uint32_t b0, b1, b2, b3;
                ldm_x4(b0, b1, b2, b3,
                       w2B + (uint32_t)(s * 8) * 4u + (uint32_t)(n16 * 16 * ST2) * 4u);
                uint32_t be[2] = { b0, b2 };
                uint32_t bo[2] = { b1, b3 };
                mma16816(acc2[0][0], a2[0][s], be);
                mma16816(acc2[0][1], a2[0][s], bo);
                mma16816(acc2[1][0], a2[1][s], be);
                mma16816(acc2[1][1], a2[1][s], bo);
            }

            // ---- fused epilogue for these 16 feats ----
            #pragma unroll
            for (int m = 0; m < 2; m++) {
                #pragma unroll
                for (int n = 0; n < 2; n++) {
                    int f = n16 * 16 + n * 8 + 2 * t;
                    float2 bb = *(const float2*)(b2f + f);
                    int elo = ebase + m * 16 + g;
                    int ehi = elo + 8;
                    if (elo < E) {
                        float2 vv = *(const float2*)(g_vl + (size_t)jv[2 * m] * 128 + f);
                        float2 o;
                        o.x = (acc2[m][n][0] + bb.x) * Cv[2 * m] * vv.x;
                        o.y = (acc2[m][n][1] + bb.y) * Cv[2 * m] * vv.y;
                        *(float2*)(out + (size_t)elo * 128 + f) = o;
                    }
                    if (ehi < E) {
                        float2 vv = *(const float2*)(g_vl + (size_t)jv[2 * m + 1] * 128 + f);
                        float2 o;
                        o.x = (acc2[m][n][2] + bb.x) * Cv[2 * m + 1] * vv.x;
                        o.y = (acc2[m][n][3] + bb.y) * Cv[2 * m + 1] * vv.y;
                        *(float2*)(out + (size_t)ehi * 128 + f) = o;
                    }
                }
            }
        }
    }
}

// ---------------------------------------------------------------------------
extern "C" void kernel_launch(void* const* d_in, const int* in_sizes, int n_in,
                              void* d_out, int out_size)
{
    const float* v          = (const float*)d_in[0];
    const float* dist       = (const float*)d_in[1];
    const float* dist_emb   = (const float*)d_in[2];
    const int*   edge_index = (const int*)d_in[3];   // int32 [2][E]
    const float* lin_w      = (const float*)d_in[4];
    const float* mlp1_w     = (const float*)d_in[5];
    const float* mlp1_b     = (const float*)d_in[6];
    const float* mlp2_w     = (const float*)d_in[7];
    const float* mlp2_b     = (const float*)d_in[8];
    float*       out        = (float*)d_out;

    const int N = in_sizes[0] / 128;
    const int E = in_sizes[1];
    const int ngroups = (E + 31) / 32;

    const size_t smemA = (size_t)(128 * 128 + 128 * 132) * sizeof(float);
    const size_t smemB = (size_t)SMEM_WORDS * 4;     // 109568 B

    cudaFuncSetAttribute(vl_kernel, cudaFuncAttributeMaxDynamicSharedMemorySize, (int)smemA);
    cudaFuncSetAttribute(edge_mma_kernel, cudaFuncAttributeMaxDynamicSharedMemorySize, (int)smemB);

    vl_kernel<<<(N + 127) / 128, 256, smemA>>>(v, lin_w, N);

    edge_mma_kernel<<<304, 256, smemB>>>(dist, dist_emb, edge_index,
                                         mlp1_w, mlp1_b, mlp2_w, mlp2_b,
                                         out, E, ngroups);
}